// round 1
// baseline (speedup 1.0000x reference)
#include <cuda_runtime.h>

#define T_STEPS 256
#define NPRE    1024
#define NPOST   1024
#define NCHUNK  4
#define TCHUNK  (T_STEPS / NCHUNK)

// Scratch (no allocations allowed anywhere)
__device__ float g_xp[NCHUNK][NPRE];
__device__ float g_yp[NCHUNK][NPOST];
__device__ float g_x[NPRE];
__device__ float g_y[NPOST];

// Kernel 1: partial weighted sums x_part[c][col] = sum_{t in chunk c} s[t][col] * 2^(t - T)
// Closed form of x_t = 0.5*x_{t-1} + 0.5*p_t  =>  x_T = sum_t p_t * 2^(t-T)
__global__ void trace_partial_kernel(const float* __restrict__ pre,
                                     const float* __restrict__ post) {
    const int col   = blockIdx.x * blockDim.x + threadIdx.x;   // 0..1023
    const int chunk = blockIdx.y;                              // 0..3
    const int which = blockIdx.z;                              // 0 = pre, 1 = post

    const float* __restrict__ s = which ? post : pre;

    const int t0 = chunk * TCHUNK;
    float acc0 = 0.0f, acc1 = 0.0f, acc2 = 0.0f, acc3 = 0.0f;

    #pragma unroll 16
    for (int k = 0; k < TCHUNK; k += 4) {
        const int t = t0 + k;
        // weight 2^(t - T); exact power of two, underflows to ~0 for early t
        // exactly where the reference's halving chain would have rounded the
        // contribution away anyway.
        float w0 = exp2f((float)(t + 0 - T_STEPS));
        float w1 = exp2f((float)(t + 1 - T_STEPS));
        float w2 = exp2f((float)(t + 2 - T_STEPS));
        float w3 = exp2f((float)(t + 3 - T_STEPS));
        acc0 = fmaf(s[(t + 0) * NPRE + col], w0, acc0);
        acc1 = fmaf(s[(t + 1) * NPRE + col], w1, acc1);
        acc2 = fmaf(s[(t + 2) * NPRE + col], w2, acc2);
        acc3 = fmaf(s[(t + 3) * NPRE + col], w3, acc3);
    }

    const float acc = (acc0 + acc1) + (acc2 + acc3);
    if (which) g_yp[chunk][col] = acc;
    else       g_xp[chunk][col] = acc;
}

// Kernel 2: reduce the 4 chunk partials into final traces
__global__ void reduce_traces_kernel() {
    const int i = blockIdx.x * blockDim.x + threadIdx.x;       // 0..2047
    if (i < NPRE) {
        g_x[i] = (g_xp[0][i] + g_xp[1][i]) + (g_xp[2][i] + g_xp[3][i]);
    } else {
        const int j = i - NPRE;
        g_y[j] = (g_yp[0][j] + g_yp[1][j]) + (g_yp[2][j] + g_yp[3][j]);
    }
}

// Kernel 3: e[i][j] = x[i]*q_last[j] - p_last[i]*y[j]
// One block per output row i; 256 threads x float4 = 1024 columns.
__global__ void outer_kernel(const float* __restrict__ pre,
                             const float* __restrict__ post,
                             float* __restrict__ e) {
    const int i = blockIdx.x;
    const float xi = g_x[i];
    const float pi = pre[(T_STEPS - 1) * NPRE + i];

    const int j4 = threadIdx.x;                                // 0..255
    const float4 y4 = reinterpret_cast<const float4*>(g_y)[j4];
    const float4 q4 = reinterpret_cast<const float4*>(post + (size_t)(T_STEPS - 1) * NPOST)[j4];

    float4 r;
    r.x = fmaf(xi, q4.x, -pi * y4.x);
    r.y = fmaf(xi, q4.y, -pi * y4.y);
    r.z = fmaf(xi, q4.z, -pi * y4.z);
    r.w = fmaf(xi, q4.w, -pi * y4.w);

    reinterpret_cast<float4*>(e)[(size_t)i * (NPOST / 4) + j4] = r;
}

extern "C" void kernel_launch(void* const* d_in, const int* in_sizes, int n_in,
                              void* d_out, int out_size) {
    const float* pre  = (const float*)d_in[0];   // [T, NPRE]
    const float* post = (const float*)d_in[1];   // [T, NPOST]
    float* e = (float*)d_out;                    // [NPRE, NPOST]

    dim3 grid1(NPRE / 256, NCHUNK, 2);
    trace_partial_kernel<<<grid1, 256>>>(pre, post);
    reduce_traces_kernel<<<(NPRE + NPOST) / 256, 256>>>();
    outer_kernel<<<NPRE, 256>>>(pre, post, e);
}

// round 4
// speedup vs baseline: 1.2294x; 1.2294x over previous
#include <cuda_runtime.h>

#define T_STEPS 256
#define NPRE    1024
#define NPOST   1024
#define K       32            // decay window: 2^-32 rel contribution beyond, negligible
#define ROWS    16            // output rows per block
#define NBLK    (NPRE / ROWS) // 64
#define NTHR    1024

// Fused STDP: e[i][j] = x[i]*q_last[j] - p_last[i]*y[j]
// with x = sum_{t} pre[t][i] * 2^(t-T), y likewise for post (TE=1 kills history of e).
__global__ __launch_bounds__(NTHR, 1)
void stdp_fused_kernel(const float* __restrict__ pre,
                       const float* __restrict__ post,
                       float* __restrict__ e) {
    __shared__ float sy[NPOST];   // y trace
    __shared__ float sq[NPOST];   // last post spikes
    __shared__ float sx[ROWS];    // x trace for this block's rows
    __shared__ float sp[ROWS];    // last pre spikes for this block's rows

    const int tid = threadIdx.x;

    // ---- Phase A: y[j] and q_last[j], one column per thread (coalesced) ----
    {
        const float* __restrict__ p0 = post + (size_t)(T_STEPS - K) * NPOST + tid;
        float acc = 0.0f;
        #pragma unroll
        for (int k = 0; k < K; k++) {
            // weight 2^(k-K): compile-time constant after unroll
            acc = fmaf(p0[(size_t)k * NPOST], exp2f((float)(k - K)), acc);
        }
        sy[tid] = acc;
        sq[tid] = p0[(size_t)(K - 1) * NPOST];  // post[T-1][tid]
    }

    // ---- Phase B: x[i], p_last[i] for the block's ROWS rows (one warp per row) ----
    {
        const int wid  = tid >> 5;
        const int lane = tid & 31;
        if (wid < ROWS) {
            const int i = blockIdx.x * ROWS + wid;
            // lane <-> timestep (K == 32 == warp size)
            float v = pre[(size_t)(T_STEPS - K + lane) * NPRE + i]
                      * exp2f((float)(lane - K));
            #pragma unroll
            for (int o = 16; o; o >>= 1) v += __shfl_xor_sync(0xFFFFFFFFu, v, o);
            if (lane == 0)  sx[wid] = v;
            if (lane == 31) sp[wid] = pre[(size_t)(T_STEPS - 1) * NPRE + i];
        }
    }

    __syncthreads();

    // ---- Phase C: rank-2 outer-product write, float4 stores ----
    const int col4 = tid & 255;   // 0..255 -> columns [col4*4, col4*4+3]
    const int rsub = tid >> 8;    // 0..3
    const float4 y4 = reinterpret_cast<const float4*>(sy)[col4];
    const float4 q4 = reinterpret_cast<const float4*>(sq)[col4];
    float4* __restrict__ out4 = reinterpret_cast<float4*>(e);

    #pragma unroll
    for (int rr = 0; rr < ROWS / 4; rr++) {
        const int r  = rsub * (ROWS / 4) + rr;
        const int i  = blockIdx.x * ROWS + r;
        const float xi = sx[r];
        const float pi = sp[r];
        float4 o;
        o.x = fmaf(xi, q4.x, -pi * y4.x);
        o.y = fmaf(xi, q4.y, -pi * y4.y);
        o.z = fmaf(xi, q4.z, -pi * y4.z);
        o.w = fmaf(xi, q4.w, -pi * y4.w);
        out4[(size_t)i * (NPOST / 4) + col4] = o;
    }
}

extern "C" void kernel_launch(void* const* d_in, const int* in_sizes, int n_in,
                              void* d_out, int out_size) {
    const float* pre  = (const float*)d_in[0];   // [T, NPRE]
    const float* post = (const float*)d_in[1];   // [T, NPOST]
    float* e = (float*)d_out;                    // [NPRE, NPOST]

    stdp_fused_kernel<<<NBLK, NTHR>>>(pre, post, e);
}